// round 5
// baseline (speedup 1.0000x reference)
#include <cuda_runtime.h>
#include <math.h>

#define NN 100000
#define EE 1600000
#define HH 64
#define KK 32
#define INCH 161   // 1 + 96 + 64

#define NT 128      // nodes per block tile
#define KT 32       // k panel
#define AS 130      // A-tile smem stride (padded, float2-aligned)

// ---------------- scratch (device globals) -------------------------------------
__device__ __align__(16) float g_xin [NN * HH];
__device__ __align__(16) float g_outf[NN * HH];
__device__ __align__(16) float g_outb[NN * HH];
__device__ __align__(16) float g_degf[NN];        // reciprocal after k_rdeg
__device__ __align__(16) float g_degb[NN];

// ---------------- packed f32x2 helpers -----------------------------------------
typedef unsigned long long ull;
static __device__ __forceinline__ ull pack2(float lo, float hi) {
    ull r;
    asm("mov.b64 %0, {%1, %2};" : "=l"(r) : "f"(lo), "f"(hi));
    return r;
}
static __device__ __forceinline__ void unpack2(ull v, float& lo, float& hi) {
    asm("mov.b64 {%0, %1}, %2;" : "=f"(lo), "=f"(hi) : "l"(v));
}
static __device__ __forceinline__ void fma2(ull& d, ull a, ull b) {
    asm("fma.rn.f32x2 %0, %1, %2, %0;" : "+l"(d) : "l"(a), "l"(b));
}
static __device__ __forceinline__ void red_add_v4(float* ptr, float a, float b,
                                                  float c, float d) {
    asm volatile("red.global.add.v4.f32 [%0], {%1, %2, %3, %4};"
                 :: "l"(ptr), "f"(a), "f"(b), "f"(c), "f"(d) : "memory");
}

// 4 nodes x 8 outs micro-kernel step for one k.
// Bpanel must already point at the k0-panel base (rows are panel-local kk).
static __device__ __forceinline__ void mk_step(ull* acc, const float* As,
                                               const float* Bpanel, int kk,
                                               int g, int o, int OUT) {
    float2 a01 = *(const float2*)&As[kk * AS + 4 * g];
    float2 a23 = *(const float2*)&As[kk * AS + 4 * g + 2];
    const float* br = &Bpanel[kk * OUT + 8 * o];
    ulonglong2 b0 = *(const ulonglong2*)br;
    ulonglong2 b1 = *(const ulonglong2*)(br + 4);
    ull a;
    a = pack2(a01.x, a01.x);
    fma2(acc[0], a, b0.x); fma2(acc[1], a, b0.y);
    fma2(acc[2], a, b1.x); fma2(acc[3], a, b1.y);
    a = pack2(a01.y, a01.y);
    fma2(acc[4], a, b0.x); fma2(acc[5], a, b0.y);
    fma2(acc[6], a, b1.x); fma2(acc[7], a, b1.y);
    a = pack2(a23.x, a23.x);
    fma2(acc[8],  a, b0.x); fma2(acc[9],  a, b0.y);
    fma2(acc[10], a, b1.x); fma2(acc[11], a, b1.y);
    a = pack2(a23.y, a23.y);
    fma2(acc[12], a, b0.x); fma2(acc[13], a, b0.y);
    fma2(acc[14], a, b1.x); fma2(acc[15], a, b1.y);
}

// ---------------- k0: zero scratch ---------------------------------------------
__global__ void k_zero() {
    int i = blockIdx.x * blockDim.x + threadIdx.x;
    float4 z = make_float4(0.f, 0.f, 0.f, 0.f);
    if (i < NN * HH / 4) {
        reinterpret_cast<float4*>(g_outf)[i] = z;
        reinterpret_cast<float4*>(g_outb)[i] = z;
    }
    if (i < NN / 4) {
        reinterpret_cast<float4*>(g_degf)[i] = z;
        reinterpret_cast<float4*>(g_degb)[i] = z;
    }
}

// ---------------- k1: weighted degrees -----------------------------------------
__global__ void k_deg(const int* __restrict__ ei, const float* __restrict__ ew) {
    int e = blockIdx.x * blockDim.x + threadIdx.x;
    if (e >= EE) return;
    int   s = ei[e];
    int   t = ei[EE + e];
    float w = ew[e];
    if (s == t || w == 0.f) return;
    atomicAdd(&g_degf[t], w);
    atomicAdd(&g_degb[s], w);
}

__global__ void k_rdeg() {
    int n = blockIdx.x * blockDim.x + threadIdx.x;
    if (n >= NN) return;
    float df = g_degf[n];
    float db = g_degb[n];
    g_degf[n] = (df > 0.f) ? (1.0f / df) : 1.0f;
    g_degb[n] = (db > 0.f) ? (1.0f / db) : 1.0f;
}

// ---------------- k2: input projection (tiled GEMM, 4x8 reg tile) --------------
__global__ __launch_bounds__(256, 3) void k_proj_t(const float* __restrict__ x,
                                                   const float* __restrict__ xh,
                                                   const float* __restrict__ h,
                                                   const float* __restrict__ Win,
                                                   const float* __restrict__ bin) {
    extern __shared__ float sm[];
    float* Bs = sm;                 // [161][64]
    float* As = sm + INCH * HH;     // [32][130]
    int tid = threadIdx.x;
    int nb  = blockIdx.x * NT;

    for (int i = tid; i < INCH * HH; i += 256) Bs[i] = Win[i];

    int o = tid & 7, g = tid >> 3;
    ull acc[16];
    {
        const float2* b2 = (const float2*)(bin + 8 * o);
        float2 p0 = b2[0], p1 = b2[1], p2 = b2[2], p3 = b2[3];
        ull B0 = pack2(p0.x, p0.y), B1 = pack2(p1.x, p1.y);
        ull B2 = pack2(p2.x, p2.y), B3 = pack2(p3.x, p3.y);
#pragma unroll
        for (int i = 0; i < 4; i++) {
            acc[i * 4 + 0] = B0; acc[i * 4 + 1] = B1;
            acc[i * 4 + 2] = B2; acc[i * 4 + 3] = B3;
        }
    }

    for (int k0 = 0; k0 < INCH; k0 += KT) {
        int kt = min(KT, INCH - k0);
        if (kt == KT) {
            for (int i = tid; i < NT * KT; i += 256) {
                int n = i >> 5, kk = i & 31;
                int k = k0 + kk;
                int gn = nb + n;
                float v = 0.f;
                if (gn < NN)
                    v = (k == 0) ? x[gn]
                      : (k < 97) ? xh[(size_t)gn * 96 + (k - 1)]
                                 : h[(size_t)gn * 64 + (k - 97)];
                As[kk * AS + n] = v;
            }
        } else {  // kt == 1 tail (k = 160 -> h[:,63])
            for (int i = tid; i < NT; i += 256) {
                int gn = nb + i;
                As[i] = (gn < NN) ? h[(size_t)gn * 64 + 63] : 0.f;
            }
        }
        __syncthreads();
        const float* Bp = Bs + k0 * HH;   // panel base
        if (kt == KT) {
#pragma unroll
            for (int kk = 0; kk < KT; kk++) mk_step(acc, As, Bp, kk, g, o, HH);
        } else {
            for (int kk = 0; kk < kt; kk++) mk_step(acc, As, Bp, kk, g, o, HH);
        }
        __syncthreads();
    }

#pragma unroll
    for (int i = 0; i < 4; i++) {
        int gn = nb + 4 * g + i;
        if (gn >= NN) break;
        float v[8];
#pragma unroll
        for (int j = 0; j < 4; j++) unpack2(acc[i * 4 + j], v[2 * j], v[2 * j + 1]);
        float4* p = (float4*)(g_xin + (size_t)gn * HH + 8 * o);
        p[0] = make_float4(v[0], v[1], v[2], v[3]);
        p[1] = make_float4(v[4], v[5], v[6], v[7]);
    }
}

// ---------------- k3: edge diffusion scatter -----------------------------------
__global__ void k_diff(const int* __restrict__ ei, const float* __restrict__ ew) {
    int idx = blockIdx.x * blockDim.x + threadIdx.x;
    int e = idx >> 4;
    int c = idx & 15;
    if (e >= EE) return;
    int   s = ei[e];
    int   t = ei[EE + e];
    float w = ew[e];
    if (s == t || w == 0.f) return;
    float wf = w * g_degf[t];
    float wb = w * g_degb[s];

    const float4* xin4 = reinterpret_cast<const float4*>(g_xin);
    float4 a = xin4[(size_t)s * 16 + c];
    red_add_v4(g_outf + (size_t)t * 64 + c * 4,
               wf * a.x, wf * a.y, wf * a.z, wf * a.w);

    float4 b = xin4[(size_t)t * 16 + c];
    red_add_v4(g_outb + (size_t)s * 64 + c * 4,
               wb * b.x, wb * b.y, wb * b.z, wb * b.w);
}

// ---------------- k4: filter GEMM (tiled) + out1/h epilogue --------------------
__global__ __launch_bounds__(256, 3) void k_filt_t(const float* __restrict__ h,
                                                   const float* __restrict__ Wf,
                                                   const float* __restrict__ bf,
                                                   float* __restrict__ out1,
                                                   float* __restrict__ hout) {
    extern __shared__ float sm[];
    float* Bs = sm;                 // [128][64]
    float* As = sm + 128 * HH;      // [32][130]
    int tid = threadIdx.x;
    int nb  = blockIdx.x * NT;

    for (int i = tid; i < 128 * HH; i += 256) Bs[i] = Wf[i];

    int o = tid & 7, g = tid >> 3;
    ull acc[16];
    {
        const float2* b2 = (const float2*)(bf + 8 * o);
        float2 p0 = b2[0], p1 = b2[1], p2 = b2[2], p3 = b2[3];
        ull B0 = pack2(p0.x, p0.y), B1 = pack2(p1.x, p1.y);
        ull B2 = pack2(p2.x, p2.y), B3 = pack2(p3.x, p3.y);
#pragma unroll
        for (int i = 0; i < 4; i++) {
            acc[i * 4 + 0] = B0; acc[i * 4 + 1] = B1;
            acc[i * 4 + 2] = B2; acc[i * 4 + 3] = B3;
        }
    }

#pragma unroll
    for (int k0 = 0; k0 < 128; k0 += KT) {
        for (int i = tid; i < NT * KT; i += 256) {
            int n = i >> 5, kk = i & 31;
            int k = k0 + kk;
            int gn = nb + n;
            float v = 0.f;
            if (gn < NN)
                v = (k < 64) ? g_outf[(size_t)gn * 64 + k]
                             : g_outb[(size_t)gn * 64 + (k - 64)];
            As[kk * AS + n] = v;
        }
        __syncthreads();
        const float* Bp = Bs + k0 * HH;   // panel base
#pragma unroll
        for (int kk = 0; kk < KT; kk++) mk_step(acc, As, Bp, kk, g, o, HH);
        __syncthreads();
    }

#pragma unroll
    for (int i = 0; i < 4; i++) {
        int gn = nb + 4 * g + i;
        if (gn >= NN) break;
        float v[8];
#pragma unroll
        for (int j = 0; j < 4; j++) unpack2(acc[i * 4 + j], v[2 * j], v[2 * j + 1]);
        float4* p = (float4*)(out1 + (size_t)gn * 128 + 8 * o);
        p[0] = make_float4(v[0], v[1], v[2], v[3]);
        p[1] = make_float4(v[4], v[5], v[6], v[7]);
        // h passthrough: out1[:,64:] and hout
        const float4* hp = (const float4*)(h + (size_t)gn * 64 + 8 * o);
        float4 h0 = hp[0], h1 = hp[1];
        float4* p2 = (float4*)(out1 + (size_t)gn * 128 + 64 + 8 * o);
        p2[0] = h0; p2[1] = h1;
        float4* ph = (float4*)(hout + (size_t)gn * 64 + 8 * o);
        ph[0] = h0; ph[1] = h1;
    }
}

// ---------------- k5: fused GMM heads (tiled GEMM, OUT=96) ---------------------
__global__ __launch_bounds__(384, 2) void k_heads_t(const float* __restrict__ out1,
                                                    const float* __restrict__ Wm,
                                                    const float* __restrict__ bm,
                                                    const float* __restrict__ Wsg,
                                                    const float* __restrict__ bsg,
                                                    const float* __restrict__ Wp,
                                                    const float* __restrict__ bp,
                                                    float* __restrict__ gmm) {
    extern __shared__ float sm[];
    float* Bs = sm;                 // [128][96] = [mu|sigma|pi]
    float* As = sm + 128 * 96;      // [32][130]
    int tid = threadIdx.x;
    int nb  = blockIdx.x * NT;

    for (int i = tid; i < 128 * 96; i += 384) {
        int k = i / 96, c = i - k * 96;
        float v = (c < 32) ? Wm[k * 32 + c]
                : (c < 64) ? Wsg[k * 32 + (c - 32)]
                           : Wp[k * 32 + (c - 64)];
        Bs[i] = v;
    }

    int o = tid % 12, g = tid / 12;       // 12 out-groups x 32 node-groups
    int c0 = 8 * o;                       // global output col base (0..88)
    const float* bias = (c0 < 32) ? (bm + c0) : (c0 < 64) ? (bsg + c0 - 32)
                                                          : (bp + c0 - 64);
    ull acc[16];
    {
        const float2* b2 = (const float2*)bias;
        float2 p0 = b2[0], p1 = b2[1], p2 = b2[2], p3 = b2[3];
        ull B0 = pack2(p0.x, p0.y), B1 = pack2(p1.x, p1.y);
        ull B2 = pack2(p2.x, p2.y), B3 = pack2(p3.x, p3.y);
#pragma unroll
        for (int i = 0; i < 4; i++) {
            acc[i * 4 + 0] = B0; acc[i * 4 + 1] = B1;
            acc[i * 4 + 2] = B2; acc[i * 4 + 3] = B3;
        }
    }

#pragma unroll
    for (int k0 = 0; k0 < 128; k0 += KT) {
        for (int i = tid; i < NT * KT; i += 384) {
            int n = i >> 5, kk = i & 31;
            int gn = nb + n;
            As[kk * AS + n] = (gn < NN) ? out1[(size_t)gn * 128 + k0 + kk] : 0.f;
        }
        __syncthreads();
        const float* Bp = Bs + k0 * 96;   // panel base
#pragma unroll
        for (int kk = 0; kk < KT; kk++) mk_step(acc, As, Bp, kk, g, o, 96);
        __syncthreads();
    }

    int lane = tid & 31;
    unsigned mask4 = 0xFu << (lane & ~3);

#pragma unroll
    for (int i = 0; i < 4; i++) {
        int gn = nb + 4 * g + i;
        bool ok = (gn < NN);
        float v[8];
#pragma unroll
        for (int j = 0; j < 4; j++) unpack2(acc[i * 4 + j], v[2 * j], v[2 * j + 1]);

        if (o < 4) {                       // mu
            if (ok) {
                float4* p = (float4*)(gmm + (size_t)gn * 96 + c0);
                p[0] = make_float4(v[0], v[1], v[2], v[3]);
                p[1] = make_float4(v[4], v[5], v[6], v[7]);
            }
        } else if (o < 8) {                // sigma = softplus
#pragma unroll
            for (int j = 0; j < 8; j++)
                v[j] = (v[j] > 20.f) ? v[j] : log1pf(__expf(v[j]));
            if (ok) {
                float4* p = (float4*)(gmm + (size_t)gn * 96 + c0);
                p[0] = make_float4(v[0], v[1], v[2], v[3]);
                p[1] = make_float4(v[4], v[5], v[6], v[7]);
            }
        } else {                           // pi = softmax over 32 (4-lane group)
            float m = v[0];
#pragma unroll
            for (int j = 1; j < 8; j++) m = fmaxf(m, v[j]);
            m = fmaxf(m, __shfl_xor_sync(mask4, m, 1));
            m = fmaxf(m, __shfl_xor_sync(mask4, m, 2));
            float s = 0.f;
#pragma unroll
            for (int j = 0; j < 8; j++) { v[j] = __expf(v[j] - m); s += v[j]; }
            s += __shfl_xor_sync(mask4, s, 1);
            s += __shfl_xor_sync(mask4, s, 2);
            float inv = 1.f / s;
#pragma unroll
            for (int j = 0; j < 8; j++) v[j] *= inv;
            if (ok) {
                float4* p = (float4*)(gmm + (size_t)gn * 96 + c0);
                p[0] = make_float4(v[0], v[1], v[2], v[3]);
                p[1] = make_float4(v[4], v[5], v[6], v[7]);
            }
        }
    }
}

// ---------------- launch -------------------------------------------------------
extern "C" void kernel_launch(void* const* d_in, const int* in_sizes, int n_in,
                              void* d_out, int out_size) {
    const float* x   = (const float*)d_in[0];
    const float* xh  = (const float*)d_in[1];
    const float* h   = (const float*)d_in[2];
    const int*   ei  = (const int*)d_in[3];
    const float* ew  = (const float*)d_in[4];
    const float* Win = (const float*)d_in[5];
    const float* bin = (const float*)d_in[6];
    const float* Wf  = (const float*)d_in[7];
    const float* bf  = (const float*)d_in[8];
    const float* Wm  = (const float*)d_in[9];
    const float* bm  = (const float*)d_in[10];
    const float* Wsg = (const float*)d_in[11];
    const float* bsg = (const float*)d_in[12];
    const float* Wp  = (const float*)d_in[13];
    const float* bp  = (const float*)d_in[14];

    float* out  = (float*)d_out;
    float* gmm  = out;                          // [N, 96]
    float* out1 = out + (size_t)NN * 96;        // [N, 128]
    float* hout = out1 + (size_t)NN * 128;      // [N, 64]

    const int SMEM_PROJ  = (INCH * HH + KT * AS) * 4;        // 57856
    const int SMEM_FILT  = (128 * HH + KT * AS) * 4;         // 49408
    const int SMEM_HEADS = (128 * 96 + KT * AS) * 4;         // 65792

    cudaFuncSetAttribute(k_proj_t,  cudaFuncAttributeMaxDynamicSharedMemorySize, SMEM_PROJ);
    cudaFuncSetAttribute(k_filt_t,  cudaFuncAttributeMaxDynamicSharedMemorySize, SMEM_FILT);
    cudaFuncSetAttribute(k_heads_t, cudaFuncAttributeMaxDynamicSharedMemorySize, SMEM_HEADS);

    int nblk = (NN + NT - 1) / NT;   // 782

    k_zero<<<(NN * HH / 4 + 255) / 256, 256>>>();
    k_deg<<<(EE + 255) / 256, 256>>>(ei, ew);
    k_rdeg<<<(NN + 255) / 256, 256>>>();
    k_proj_t<<<nblk, 256, SMEM_PROJ>>>(x, xh, h, Win, bin);
    k_diff<<<(EE * 16) / 256, 256>>>(ei, ew);
    k_filt_t<<<nblk, 256, SMEM_FILT>>>(h, Wf, bf, out1, hout);
    k_heads_t<<<nblk, 384, SMEM_HEADS>>>(out1, Wm, bm, Wsg, bsg, Wp, bp, gmm);
}

// round 8
// speedup vs baseline: 1.0835x; 1.0835x over previous
#include <cuda_runtime.h>
#include <math.h>

#define NN 100000
#define EE 1600000
#define HH 64
#define KK 32
#define INCH 161   // 1 + 96 + 64

// ---------------- scratch (device globals) -------------------------------------
__device__ __align__(16) float g_xin [NN * HH];
__device__ __align__(16) float g_outf[NN * HH];
__device__ __align__(16) float g_outb[NN * HH];
__device__ __align__(16) float g_degf[NN];        // reciprocal after k_rdeg
__device__ __align__(16) float g_degb[NN];

// ---------------- packed f32x2 helpers -----------------------------------------
typedef unsigned long long ull;
static __device__ __forceinline__ ull pack2(float lo, float hi) {
    ull r;
    asm("mov.b64 %0, {%1, %2};" : "=l"(r) : "f"(lo), "f"(hi));
    return r;
}
static __device__ __forceinline__ void unpack2(ull v, float& lo, float& hi) {
    asm("mov.b64 {%0, %1}, %2;" : "=f"(lo), "=f"(hi) : "l"(v));
}
static __device__ __forceinline__ void fma2(ull& d, ull a, ull b) {
    asm("fma.rn.f32x2 %0, %1, %2, %0;" : "+l"(d) : "l"(a), "l"(b));
}
static __device__ __forceinline__ void red_add_v4(float* ptr, float a, float b,
                                                  float c, float d) {
    asm volatile("red.global.add.v4.f32 [%0], {%1, %2, %3, %4};"
                 :: "l"(ptr), "f"(a), "f"(b), "f"(c), "f"(d) : "memory");
}

// 2 nodes x 32 outputs: one k-step. Wr = &Ws[k*OUT + 32*r] (warp-uniform -> broadcast LDS)
static __device__ __forceinline__ void step2(ull* acc0, ull* acc1,
                                             const float* Wr, float a0, float a1) {
    const ulonglong2* w = (const ulonglong2*)Wr;
    ull A0 = pack2(a0, a0), A1 = pack2(a1, a1);
#pragma unroll
    for (int j = 0; j < 8; j++) {
        ulonglong2 wv = w[j];
        fma2(acc0[2 * j], A0, wv.x); fma2(acc0[2 * j + 1], A0, wv.y);
        fma2(acc1[2 * j], A1, wv.x); fma2(acc1[2 * j + 1], A1, wv.y);
    }
}

static __device__ __forceinline__ void init_acc(ull* acc0, ull* acc1,
                                                const float* bias32) {
    const ulonglong2* bb = (const ulonglong2*)bias32;
#pragma unroll
    for (int j = 0; j < 8; j++) {
        ulonglong2 b = bb[j];
        acc0[2 * j] = b.x; acc0[2 * j + 1] = b.y;
        acc1[2 * j] = b.x; acc1[2 * j + 1] = b.y;
    }
}

static __device__ __forceinline__ void store32(float* dst, const ull* acc) {
#pragma unroll
    for (int j = 0; j < 8; j++) {
        float l0, h0, l1, h1;
        unpack2(acc[2 * j], l0, h0);
        unpack2(acc[2 * j + 1], l1, h1);
        ((float4*)dst)[j] = make_float4(l0, h0, l1, h1);
    }
}

// ---------------- k0: zero scratch ---------------------------------------------
__global__ void k_zero() {
    int i = blockIdx.x * blockDim.x + threadIdx.x;
    float4 z = make_float4(0.f, 0.f, 0.f, 0.f);
    if (i < NN * HH / 4) {
        reinterpret_cast<float4*>(g_outf)[i] = z;
        reinterpret_cast<float4*>(g_outb)[i] = z;
    }
    if (i < NN / 4) {
        reinterpret_cast<float4*>(g_degf)[i] = z;
        reinterpret_cast<float4*>(g_degb)[i] = z;
    }
}

// ---------------- k1: weighted degrees -----------------------------------------
__global__ void k_deg(const int* __restrict__ ei, const float* __restrict__ ew) {
    int e = blockIdx.x * blockDim.x + threadIdx.x;
    if (e >= EE) return;
    int   s = ei[e];
    int   t = ei[EE + e];
    float w = ew[e];
    if (s == t || w == 0.f) return;
    atomicAdd(&g_degf[t], w);
    atomicAdd(&g_degb[s], w);
}

__global__ void k_rdeg() {
    int n = blockIdx.x * blockDim.x + threadIdx.x;
    if (n >= NN) return;
    float df = g_degf[n];
    float db = g_degb[n];
    g_degf[n] = (df > 0.f) ? (1.0f / df) : 1.0f;
    g_degb[n] = (db > 0.f) ? (1.0f / db) : 1.0f;
}

// ---------------- k2: input projection (2 nodes x 32 outs / thread) ------------
__global__ __launch_bounds__(256, 2) void k_proj2(const float* __restrict__ x,
                                                  const float* __restrict__ xh,
                                                  const float* __restrict__ h,
                                                  const float* __restrict__ Win,
                                                  const float* __restrict__ bin) {
    __shared__ __align__(16) float Ws[INCH * HH];   // 41216 B
    int tid = threadIdx.x;
    for (int i = tid; i < INCH * HH; i += 256) Ws[i] = Win[i];
    __syncthreads();

    int r = tid & 1;                 // output half: cols 32r..32r+31
    int p = tid >> 1;                // node pair
    int n0 = blockIdx.x * 256 + 2 * p;
    int n1 = n0 + 1;
    int m0 = min(n0, NN - 1), m1 = min(n1, NN - 1);

    ull acc0[16], acc1[16];
    init_acc(acc0, acc1, bin + 32 * r);
    const float* W = Ws + 32 * r;

    // k = 0 : x
    step2(acc0, acc1, W, x[m0], x[m1]);

    // k = 1..96 : x_hat_1
    const float4* A0 = (const float4*)(xh + (size_t)m0 * 96);
    const float4* A1 = (const float4*)(xh + (size_t)m1 * 96);
#pragma unroll 2
    for (int kk = 0; kk < 24; kk++) {
        float4 a = A0[kk], b = A1[kk];
        const float* Wk = W + (1 + 4 * kk) * HH;
        step2(acc0, acc1, Wk,          a.x, b.x);
        step2(acc0, acc1, Wk + HH,     a.y, b.y);
        step2(acc0, acc1, Wk + 2 * HH, a.z, b.z);
        step2(acc0, acc1, Wk + 3 * HH, a.w, b.w);
    }
    // k = 97..160 : h
    const float4* H0 = (const float4*)(h + (size_t)m0 * 64);
    const float4* H1 = (const float4*)(h + (size_t)m1 * 64);
#pragma unroll 2
    for (int kk = 0; kk < 16; kk++) {
        float4 a = H0[kk], b = H1[kk];
        const float* Wk = W + (97 + 4 * kk) * HH;
        step2(acc0, acc1, Wk,          a.x, b.x);
        step2(acc0, acc1, Wk + HH,     a.y, b.y);
        step2(acc0, acc1, Wk + 2 * HH, a.z, b.z);
        step2(acc0, acc1, Wk + 3 * HH, a.w, b.w);
    }

    if (n0 < NN) store32(g_xin + (size_t)n0 * 64 + 32 * r, acc0);
    if (n1 < NN) store32(g_xin + (size_t)n1 * 64 + 32 * r, acc1);
}

// ---------------- k3: edge diffusion scatter -----------------------------------
__global__ void k_diff(const int* __restrict__ ei, const float* __restrict__ ew) {
    int idx = blockIdx.x * blockDim.x + threadIdx.x;
    int e = idx >> 4;
    int c = idx & 15;
    if (e >= EE) return;
    int   s = ei[e];
    int   t = ei[EE + e];
    float w = ew[e];
    if (s == t || w == 0.f) return;
    float wf = w * g_degf[t];
    float wb = w * g_degb[s];

    const float4* xin4 = reinterpret_cast<const float4*>(g_xin);
    float4 a = xin4[(size_t)s * 16 + c];
    red_add_v4(g_outf + (size_t)t * 64 + c * 4,
               wf * a.x, wf * a.y, wf * a.z, wf * a.w);

    float4 b = xin4[(size_t)t * 16 + c];
    red_add_v4(g_outb + (size_t)s * 64 + c * 4,
               wb * b.x, wb * b.y, wb * b.z, wb * b.w);
}

// ---------------- k4: filter GEMM (2 nodes x 32 outs) + out1/h epilogue --------
__global__ __launch_bounds__(256, 2) void k_filt2(const float* __restrict__ h,
                                                  const float* __restrict__ Wf,
                                                  const float* __restrict__ bf,
                                                  float* __restrict__ out1,
                                                  float* __restrict__ hout) {
    __shared__ __align__(16) float Ws[128 * HH];    // 32 KB
    int tid = threadIdx.x;
    for (int i = tid; i < 128 * HH; i += 256) Ws[i] = Wf[i];
    __syncthreads();

    int r = tid & 1;
    int p = tid >> 1;
    int n0 = blockIdx.x * 256 + 2 * p;
    int n1 = n0 + 1;
    int m0 = min(n0, NN - 1), m1 = min(n1, NN - 1);

    ull acc0[16], acc1[16];
    init_acc(acc0, acc1, bf + 32 * r);
    const float* W = Ws + 32 * r;

    const float4* F0 = (const float4*)(g_outf + (size_t)m0 * 64);
    const float4* F1 = (const float4*)(g_outf + (size_t)m1 * 64);
#pragma unroll 2
    for (int kk = 0; kk < 16; kk++) {
        float4 a = F0[kk], b = F1[kk];
        const float* Wk = W + (4 * kk) * HH;
        step2(acc0, acc1, Wk,          a.x, b.x);
        step2(acc0, acc1, Wk + HH,     a.y, b.y);
        step2(acc0, acc1, Wk + 2 * HH, a.z, b.z);
        step2(acc0, acc1, Wk + 3 * HH, a.w, b.w);
    }
    const float4* B0 = (const float4*)(g_outb + (size_t)m0 * 64);
    const float4* B1 = (const float4*)(g_outb + (size_t)m1 * 64);
#pragma unroll 2
    for (int kk = 0; kk < 16; kk++) {
        float4 a = B0[kk], b = B1[kk];
        const float* Wk = W + (64 + 4 * kk) * HH;
        step2(acc0, acc1, Wk,          a.x, b.x);
        step2(acc0, acc1, Wk + HH,     a.y, b.y);
        step2(acc0, acc1, Wk + 2 * HH, a.z, b.z);
        step2(acc0, acc1, Wk + 3 * HH, a.w, b.w);
    }

    if (n0 < NN) {
        store32(out1 + (size_t)n0 * 128 + 32 * r, acc0);
        const float4* hp = (const float4*)(h + (size_t)n0 * 64 + 32 * r);
        float4* o2 = (float4*)(out1 + (size_t)n0 * 128 + 64 + 32 * r);
        float4* ho = (float4*)(hout + (size_t)n0 * 64 + 32 * r);
#pragma unroll
        for (int j = 0; j < 8; j++) { float4 v = hp[j]; o2[j] = v; ho[j] = v; }
    }
    if (n1 < NN) {
        store32(out1 + (size_t)n1 * 128 + 32 * r, acc1);
        const float4* hp = (const float4*)(h + (size_t)n1 * 64 + 32 * r);
        float4* o2 = (float4*)(out1 + (size_t)n1 * 128 + 64 + 32 * r);
        float4* ho = (float4*)(hout + (size_t)n1 * 64 + 32 * r);
#pragma unroll
        for (int j = 0; j < 8; j++) { float4 v = hp[j]; o2[j] = v; ho[j] = v; }
    }
}

// ---------------- k5: fused GMM heads (2 nodes x one 32-wide head / thread) ----
// 384 threads: r = tid>>7 (0=mu,1=sigma,2=pi; warp-uniform), p = tid&127.
__global__ __launch_bounds__(384, 1) void k_heads2(const float* __restrict__ out1,
                                                   const float* __restrict__ Wm,
                                                   const float* __restrict__ bm,
                                                   const float* __restrict__ Wsg,
                                                   const float* __restrict__ bsg,
                                                   const float* __restrict__ Wp,
                                                   const float* __restrict__ bp,
                                                   float* __restrict__ gmm) {
    extern __shared__ float Ws[];                   // [128][96] = [mu|sigma|pi]
    int tid = threadIdx.x;
    for (int i = tid; i < 128 * 96; i += 384) {
        int k = i / 96, c = i - k * 96;
        Ws[i] = (c < 32) ? Wm[k * 32 + c]
              : (c < 64) ? Wsg[k * 32 + (c - 32)]
                         : Wp[k * 32 + (c - 64)];
    }
    __syncthreads();

    int r = tid >> 7;                // head selector (warp-uniform)
    int p = tid & 127;
    int n0 = blockIdx.x * 256 + 2 * p;
    int n1 = n0 + 1;
    int m0 = min(n0, NN - 1), m1 = min(n1, NN - 1);

    const float* bias = (r == 0) ? bm : (r == 1) ? bsg : bp;
    ull acc0[16], acc1[16];
    init_acc(acc0, acc1, bias);
    const float* W = Ws + 32 * r;

    const float4* A0 = (const float4*)(out1 + (size_t)m0 * 128);
    const float4* A1 = (const float4*)(out1 + (size_t)m1 * 128);
#pragma unroll 2
    for (int kk = 0; kk < 32; kk++) {
        float4 a = A0[kk], b = A1[kk];
        const float* Wk = W + (4 * kk) * 96;
        step2(acc0, acc1, Wk,          a.x, b.x);
        step2(acc0, acc1, Wk + 96,     a.y, b.y);
        step2(acc0, acc1, Wk + 192,    a.z, b.z);
        step2(acc0, acc1, Wk + 288,    a.w, b.w);
    }

#pragma unroll
    for (int i = 0; i < 2; i++) {
        int gn = (i == 0) ? n0 : n1;
        if (gn >= NN) break;
        ull* acc = (i == 0) ? acc0 : acc1;
        float v[32];
#pragma unroll
        for (int j = 0; j < 16; j++) unpack2(acc[j], v[2 * j], v[2 * j + 1]);

        if (r == 1) {                  // sigma = softplus
#pragma unroll
            for (int j = 0; j < 32; j++)
                v[j] = (v[j] > 20.f) ? v[j] : log1pf(__expf(v[j]));
        } else if (r == 2) {           // pi = softmax over 32 (in-thread)
            float m = v[0];
#pragma unroll
            for (int j = 1; j < 32; j++) m = fmaxf(m, v[j]);
            float s = 0.f;
#pragma unroll
            for (int j = 0; j < 32; j++) { v[j] = __expf(v[j] - m); s += v[j]; }
            float inv = 1.f / s;
#pragma unroll
            for (int j = 0; j < 32; j++) v[j] *= inv;
        }
        float4* o = (float4*)(gmm + (size_t)gn * 96 + 32 * r);
#pragma unroll
        for (int j = 0; j < 8; j++)
            o[j] = make_float4(v[4 * j], v[4 * j + 1], v[4 * j + 2], v[4 * j + 3]);
    }
}

// ---------------- launch -------------------------------------------------------
extern "C" void kernel_launch(void* const* d_in, const int* in_sizes, int n_in,
                              void* d_out, int out_size) {
    const float* x   = (const float*)d_in[0];
    const float* xh  = (const float*)d_in[1];
    const float* h   = (const float*)d_in[2];
    const int*   ei  = (const int*)d_in[3];
    const float* ew  = (const float*)d_in[4];
    const float* Win = (const float*)d_in[5];
    const float* bin = (const float*)d_in[6];
    const float* Wf  = (const float*)d_in[7];
    const float* bf  = (const float*)d_in[8];
    const float* Wm  = (const float*)d_in[9];
    const float* bm  = (const float*)d_in[10];
    const float* Wsg = (const float*)d_in[11];
    const float* bsg = (const float*)d_in[12];
    const float* Wp  = (const float*)d_in[13];
    const float* bp  = (const float*)d_in[14];

    float* out  = (float*)d_out;
    float* gmm  = out;                          // [N, 96]
    float* out1 = out + (size_t)NN * 96;        // [N, 128]
    float* hout = out1 + (size_t)NN * 128;      // [N, 64]

    const int SMEM_HEADS = 128 * 96 * 4;        // 49152
    cudaFuncSetAttribute(k_heads2, cudaFuncAttributeMaxDynamicSharedMemorySize,
                         SMEM_HEADS);

    int nb2 = (NN + 255) / 256;   // 391 blocks, 256 nodes each

    k_zero<<<(NN * HH / 4 + 255) / 256, 256>>>();
    k_deg<<<(EE + 255) / 256, 256>>>(ei, ew);
    k_rdeg<<<(NN + 255) / 256, 256>>>();
    k_proj2<<<nb2, 256>>>(x, xh, h, Win, bin);
    k_diff<<<(EE * 16) / 256, 256>>>(ei, ew);
    k_filt2<<<nb2, 256>>>(h, Wf, bf, out1, hout);
    k_heads2<<<nb2, 384, SMEM_HEADS>>>(out1, Wm, bm, Wsg, bsg, Wp, bp, gmm);
}

// round 9
// speedup vs baseline: 1.0844x; 1.0008x over previous
#include <cuda_runtime.h>
#include <math.h>

#define NN 100000
#define EE 1600000
#define HH 64
#define KK 32
#define INCH 161   // 1 + 96 + 64

// ---------------- scratch (device globals) -------------------------------------
__device__ __align__(16) float g_xin [NN * HH];
__device__ __align__(16) float g_outf[NN * HH];
__device__ __align__(16) float g_outb[NN * HH];
__device__ __align__(16) float g_degf[NN];        // reciprocal after k_rdeg
__device__ __align__(16) float g_degb[NN];

// ---------------- packed f32x2 helpers -----------------------------------------
typedef unsigned long long ull;
static __device__ __forceinline__ ull pack2(float lo, float hi) {
    ull r;
    asm("mov.b64 %0, {%1, %2};" : "=l"(r) : "f"(lo), "f"(hi));
    return r;
}
static __device__ __forceinline__ void unpack2(ull v, float& lo, float& hi) {
    asm("mov.b64 {%0, %1}, %2;" : "=f"(lo), "=f"(hi) : "l"(v));
}
static __device__ __forceinline__ void fma2(ull& d, ull a, ull b) {
    asm("fma.rn.f32x2 %0, %1, %2, %0;" : "+l"(d) : "l"(a), "l"(b));
}
static __device__ __forceinline__ void red_add_v4(float* ptr, float a, float b,
                                                  float c, float d) {
    asm volatile("red.global.add.v4.f32 [%0], {%1, %2, %3, %4};"
                 :: "l"(ptr), "f"(a), "f"(b), "f"(c), "f"(d) : "memory");
}

// 2 nodes x 32 outputs: one k-step. Wr = &Ws[k*OUT + 32*r] (warp-uniform -> broadcast LDS)
static __device__ __forceinline__ void step2(ull* acc0, ull* acc1,
                                             const float* Wr, float a0, float a1) {
    const ulonglong2* w = (const ulonglong2*)Wr;
    ull A0 = pack2(a0, a0), A1 = pack2(a1, a1);
#pragma unroll
    for (int j = 0; j < 8; j++) {
        ulonglong2 wv = w[j];
        fma2(acc0[2 * j], A0, wv.x); fma2(acc0[2 * j + 1], A0, wv.y);
        fma2(acc1[2 * j], A1, wv.x); fma2(acc1[2 * j + 1], A1, wv.y);
    }
}

static __device__ __forceinline__ void init_acc(ull* acc0, ull* acc1,
                                                const float* bias32) {
    const ulonglong2* bb = (const ulonglong2*)bias32;
#pragma unroll
    for (int j = 0; j < 8; j++) {
        ulonglong2 b = bb[j];
        acc0[2 * j] = b.x; acc0[2 * j + 1] = b.y;
        acc1[2 * j] = b.x; acc1[2 * j + 1] = b.y;
    }
}

static __device__ __forceinline__ void store32(float* dst, const ull* acc) {
#pragma unroll
    for (int j = 0; j < 8; j++) {
        float l0, h0, l1, h1;
        unpack2(acc[2 * j], l0, h0);
        unpack2(acc[2 * j + 1], l1, h1);
        ((float4*)dst)[j] = make_float4(l0, h0, l1, h1);
    }
}

// ---------------- k0: zero scratch ---------------------------------------------
__global__ void k_zero() {
    int i = blockIdx.x * blockDim.x + threadIdx.x;
    float4 z = make_float4(0.f, 0.f, 0.f, 0.f);
    if (i < NN * HH / 4) {
        reinterpret_cast<float4*>(g_outf)[i] = z;
        reinterpret_cast<float4*>(g_outb)[i] = z;
    }
    if (i < NN / 4) {
        reinterpret_cast<float4*>(g_degf)[i] = z;
        reinterpret_cast<float4*>(g_degb)[i] = z;
    }
}

// ---------------- k1: weighted degrees -----------------------------------------
__global__ void k_deg(const int* __restrict__ ei, const float* __restrict__ ew) {
    int e = blockIdx.x * blockDim.x + threadIdx.x;
    if (e >= EE) return;
    int   s = ei[e];
    int   t = ei[EE + e];
    float w = ew[e];
    if (s == t || w == 0.f) return;
    atomicAdd(&g_degf[t], w);
    atomicAdd(&g_degb[s], w);
}

__global__ void k_rdeg() {
    int n = blockIdx.x * blockDim.x + threadIdx.x;
    if (n >= NN) return;
    float df = g_degf[n];
    float db = g_degb[n];
    g_degf[n] = (df > 0.f) ? (1.0f / df) : 1.0f;
    g_degb[n] = (db > 0.f) ? (1.0f / db) : 1.0f;
}

// ---------------- k2: input projection (2 nodes x 32 outs / thread) ------------
__global__ __launch_bounds__(256, 2) void k_proj2(const float* __restrict__ x,
                                                  const float* __restrict__ xh,
                                                  const float* __restrict__ h,
                                                  const float* __restrict__ Win,
                                                  const float* __restrict__ bin) {
    __shared__ __align__(16) float Ws[INCH * HH];   // 41216 B
    int tid = threadIdx.x;
    for (int i = tid; i < INCH * HH; i += 256) Ws[i] = Win[i];
    __syncthreads();

    int r = tid & 1;                 // output half: cols 32r..32r+31
    int p = tid >> 1;                // node pair
    int n0 = blockIdx.x * 256 + 2 * p;
    int n1 = n0 + 1;
    int m0 = min(n0, NN - 1), m1 = min(n1, NN - 1);

    ull acc0[16], acc1[16];
    init_acc(acc0, acc1, bin + 32 * r);
    const float* W = Ws + 32 * r;

    // k = 0 : x
    step2(acc0, acc1, W, x[m0], x[m1]);

    // k = 1..96 : x_hat_1
    const float4* A0 = (const float4*)(xh + (size_t)m0 * 96);
    const float4* A1 = (const float4*)(xh + (size_t)m1 * 96);
#pragma unroll 2
    for (int kk = 0; kk < 24; kk++) {
        float4 a = A0[kk], b = A1[kk];
        const float* Wk = W + (1 + 4 * kk) * HH;
        step2(acc0, acc1, Wk,          a.x, b.x);
        step2(acc0, acc1, Wk + HH,     a.y, b.y);
        step2(acc0, acc1, Wk + 2 * HH, a.z, b.z);
        step2(acc0, acc1, Wk + 3 * HH, a.w, b.w);
    }
    // k = 97..160 : h
    const float4* H0 = (const float4*)(h + (size_t)m0 * 64);
    const float4* H1 = (const float4*)(h + (size_t)m1 * 64);
#pragma unroll 2
    for (int kk = 0; kk < 16; kk++) {
        float4 a = H0[kk], b = H1[kk];
        const float* Wk = W + (97 + 4 * kk) * HH;
        step2(acc0, acc1, Wk,          a.x, b.x);
        step2(acc0, acc1, Wk + HH,     a.y, b.y);
        step2(acc0, acc1, Wk + 2 * HH, a.z, b.z);
        step2(acc0, acc1, Wk + 3 * HH, a.w, b.w);
    }

    if (n0 < NN) store32(g_xin + (size_t)n0 * 64 + 32 * r, acc0);
    if (n1 < NN) store32(g_xin + (size_t)n1 * 64 + 32 * r, acc1);
}

// ---------------- k3: edge diffusion scatter -----------------------------------
__global__ void k_diff(const int* __restrict__ ei, const float* __restrict__ ew) {
    int idx = blockIdx.x * blockDim.x + threadIdx.x;
    int e = idx >> 4;
    int c = idx & 15;
    if (e >= EE) return;
    int   s = ei[e];
    int   t = ei[EE + e];
    float w = ew[e];
    if (s == t || w == 0.f) return;
    float wf = w * g_degf[t];
    float wb = w * g_degb[s];

    const float4* xin4 = reinterpret_cast<const float4*>(g_xin);
    float4 a = xin4[(size_t)s * 16 + c];
    red_add_v4(g_outf + (size_t)t * 64 + c * 4,
               wf * a.x, wf * a.y, wf * a.z, wf * a.w);

    float4 b = xin4[(size_t)t * 16 + c];
    red_add_v4(g_outb + (size_t)s * 64 + c * 4,
               wb * b.x, wb * b.y, wb * b.z, wb * b.w);
}

// ---------------- k4: filter GEMM (2 nodes x 32 outs) + out1/h epilogue --------
__global__ __launch_bounds__(256, 2) void k_filt2(const float* __restrict__ h,
                                                  const float* __restrict__ Wf,
                                                  const float* __restrict__ bf,
                                                  float* __restrict__ out1,
                                                  float* __restrict__ hout) {
    __shared__ __align__(16) float Ws[128 * HH];    // 32 KB
    int tid = threadIdx.x;
    for (int i = tid; i < 128 * HH; i += 256) Ws[i] = Wf[i];
    __syncthreads();

    int r = tid & 1;
    int p = tid >> 1;
    int n0 = blockIdx.x * 256 + 2 * p;
    int n1 = n0 + 1;
    int m0 = min(n0, NN - 1), m1 = min(n1, NN - 1);

    ull acc0[16], acc1[16];
    init_acc(acc0, acc1, bf + 32 * r);
    const float* W = Ws + 32 * r;

    const float4* F0 = (const float4*)(g_outf + (size_t)m0 * 64);
    const float4* F1 = (const float4*)(g_outf + (size_t)m1 * 64);
#pragma unroll 2
    for (int kk = 0; kk < 16; kk++) {
        float4 a = F0[kk], b = F1[kk];
        const float* Wk = W + (4 * kk) * HH;
        step2(acc0, acc1, Wk,          a.x, b.x);
        step2(acc0, acc1, Wk + HH,     a.y, b.y);
        step2(acc0, acc1, Wk + 2 * HH, a.z, b.z);
        step2(acc0, acc1, Wk + 3 * HH, a.w, b.w);
    }
    const float4* B0 = (const float4*)(g_outb + (size_t)m0 * 64);
    const float4* B1 = (const float4*)(g_outb + (size_t)m1 * 64);
#pragma unroll 2
    for (int kk = 0; kk < 16; kk++) {
        float4 a = B0[kk], b = B1[kk];
        const float* Wk = W + (64 + 4 * kk) * HH;
        step2(acc0, acc1, Wk,          a.x, b.x);
        step2(acc0, acc1, Wk + HH,     a.y, b.y);
        step2(acc0, acc1, Wk + 2 * HH, a.z, b.z);
        step2(acc0, acc1, Wk + 3 * HH, a.w, b.w);
    }

    if (n0 < NN) {
        store32(out1 + (size_t)n0 * 128 + 32 * r, acc0);
        const float4* hp = (const float4*)(h + (size_t)n0 * 64 + 32 * r);
        float4* o2 = (float4*)(out1 + (size_t)n0 * 128 + 64 + 32 * r);
        float4* ho = (float4*)(hout + (size_t)n0 * 64 + 32 * r);
#pragma unroll
        for (int j = 0; j < 8; j++) { float4 v = hp[j]; o2[j] = v; ho[j] = v; }
    }
    if (n1 < NN) {
        store32(out1 + (size_t)n1 * 128 + 32 * r, acc1);
        const float4* hp = (const float4*)(h + (size_t)n1 * 64 + 32 * r);
        float4* o2 = (float4*)(out1 + (size_t)n1 * 128 + 64 + 32 * r);
        float4* ho = (float4*)(hout + (size_t)n1 * 64 + 32 * r);
#pragma unroll
        for (int j = 0; j < 8; j++) { float4 v = hp[j]; o2[j] = v; ho[j] = v; }
    }
}

// ---------------- k5: fused GMM heads (2 nodes x one 32-wide head / thread) ----
// 384 threads: r = tid>>7 (0=mu,1=sigma,2=pi; warp-uniform), p = tid&127.
__global__ __launch_bounds__(384, 1) void k_heads2(const float* __restrict__ out1,
                                                   const float* __restrict__ Wm,
                                                   const float* __restrict__ bm,
                                                   const float* __restrict__ Wsg,
                                                   const float* __restrict__ bsg,
                                                   const float* __restrict__ Wp,
                                                   const float* __restrict__ bp,
                                                   float* __restrict__ gmm) {
    extern __shared__ float Ws[];                   // [128][96] = [mu|sigma|pi]
    int tid = threadIdx.x;
    for (int i = tid; i < 128 * 96; i += 384) {
        int k = i / 96, c = i - k * 96;
        Ws[i] = (c < 32) ? Wm[k * 32 + c]
              : (c < 64) ? Wsg[k * 32 + (c - 32)]
                         : Wp[k * 32 + (c - 64)];
    }
    __syncthreads();

    int r = tid >> 7;                // head selector (warp-uniform)
    int p = tid & 127;
    int n0 = blockIdx.x * 256 + 2 * p;
    int n1 = n0 + 1;
    int m0 = min(n0, NN - 1), m1 = min(n1, NN - 1);

    const float* bias = (r == 0) ? bm : (r == 1) ? bsg : bp;
    ull acc0[16], acc1[16];
    init_acc(acc0, acc1, bias);
    const float* W = Ws + 32 * r;

    const float4* A0 = (const float4*)(out1 + (size_t)m0 * 128);
    const float4* A1 = (const float4*)(out1 + (size_t)m1 * 128);
#pragma unroll 2
    for (int kk = 0; kk < 32; kk++) {
        float4 a = A0[kk], b = A1[kk];
        const float* Wk = W + (4 * kk) * 96;
        step2(acc0, acc1, Wk,          a.x, b.x);
        step2(acc0, acc1, Wk + 96,     a.y, b.y);
        step2(acc0, acc1, Wk + 192,    a.z, b.z);
        step2(acc0, acc1, Wk + 288,    a.w, b.w);
    }

#pragma unroll
    for (int i = 0; i < 2; i++) {
        int gn = (i == 0) ? n0 : n1;
        if (gn >= NN) break;
        ull* acc = (i == 0) ? acc0 : acc1;
        float v[32];
#pragma unroll
        for (int j = 0; j < 16; j++) unpack2(acc[j], v[2 * j], v[2 * j + 1]);

        if (r == 1) {                  // sigma = softplus
#pragma unroll
            for (int j = 0; j < 32; j++)
                v[j] = (v[j] > 20.f) ? v[j] : log1pf(__expf(v[j]));
        } else if (r == 2) {           // pi = softmax over 32 (in-thread)
            float m = v[0];
#pragma unroll
            for (int j = 1; j < 32; j++) m = fmaxf(m, v[j]);
            float s = 0.f;
#pragma unroll
            for (int j = 0; j < 32; j++) { v[j] = __expf(v[j] - m); s += v[j]; }
            float inv = 1.f / s;
#pragma unroll
            for (int j = 0; j < 32; j++) v[j] *= inv;
        }
        float4* o = (float4*)(gmm + (size_t)gn * 96 + 32 * r);
#pragma unroll
        for (int j = 0; j < 8; j++)
            o[j] = make_float4(v[4 * j], v[4 * j + 1], v[4 * j + 2], v[4 * j + 3]);
    }
}

// ---------------- launch -------------------------------------------------------
extern "C" void kernel_launch(void* const* d_in, const int* in_sizes, int n_in,
                              void* d_out, int out_size) {
    const float* x   = (const float*)d_in[0];
    const float* xh  = (const float*)d_in[1];
    const float* h   = (const float*)d_in[2];
    const int*   ei  = (const int*)d_in[3];
    const float* ew  = (const float*)d_in[4];
    const float* Win = (const float*)d_in[5];
    const float* bin = (const float*)d_in[6];
    const float* Wf  = (const float*)d_in[7];
    const float* bf  = (const float*)d_in[8];
    const float* Wm  = (const float*)d_in[9];
    const float* bm  = (const float*)d_in[10];
    const float* Wsg = (const float*)d_in[11];
    const float* bsg = (const float*)d_in[12];
    const float* Wp  = (const float*)d_in[13];
    const float* bp  = (const float*)d_in[14];

    float* out  = (float*)d_out;
    float* gmm  = out;                          // [N, 96]
    float* out1 = out + (size_t)NN * 96;        // [N, 128]
    float* hout = out1 + (size_t)NN * 128;      // [N, 64]

    const int SMEM_HEADS = 128 * 96 * 4;        // 49152
    cudaFuncSetAttribute(k_heads2, cudaFuncAttributeMaxDynamicSharedMemorySize,
                         SMEM_HEADS);

    int nb2 = (NN + 255) / 256;   // 391 blocks, 256 nodes each

    k_zero<<<(NN * HH / 4 + 255) / 256, 256>>>();
    k_deg<<<(EE + 255) / 256, 256>>>(ei, ew);
    k_rdeg<<<(NN + 255) / 256, 256>>>();
    k_proj2<<<nb2, 256>>>(x, xh, h, Win, bin);
    k_diff<<<(EE * 16) / 256, 256>>>(ei, ew);
    k_filt2<<<nb2, 256>>>(h, Wf, bf, out1, hout);
    k_heads2<<<nb2, 384, SMEM_HEADS>>>(out1, Wm, bm, Wsg, bsg, Wp, bp, gmm);
}

// round 10
// speedup vs baseline: 1.1051x; 1.0191x over previous
#include <cuda_runtime.h>
#include <math.h>

#define NN 100000
#define EE 1600000
#define HH 64
#define KK 32
#define INCH 161   // 1 + 96 + 64

// ---------------- scratch (device globals) -------------------------------------
__device__ __align__(16) float g_xin [NN * HH];
__device__ __align__(16) float g_outf[NN * HH];
__device__ __align__(16) float g_outb[NN * HH];
__device__ __align__(16) float g_degf[NN];        // reciprocal after k_rdeg
__device__ __align__(16) float g_degb[NN];

// ---------------- packed f32x2 helpers -----------------------------------------
typedef unsigned long long ull;
static __device__ __forceinline__ ull pack2(float lo, float hi) {
    ull r;
    asm("mov.b64 %0, {%1, %2};" : "=l"(r) : "f"(lo), "f"(hi));
    return r;
}
static __device__ __forceinline__ void unpack2(ull v, float& lo, float& hi) {
    asm("mov.b64 {%0, %1}, %2;" : "=f"(lo), "=f"(hi) : "l"(v));
}
static __device__ __forceinline__ void fma2(ull& d, ull a, ull b) {
    asm("fma.rn.f32x2 %0, %1, %2, %0;" : "+l"(d) : "l"(a), "l"(b));
}
static __device__ __forceinline__ void red_add_v4(float* ptr, float a, float b,
                                                  float c, float d) {
    asm volatile("red.global.add.v4.f32 [%0], {%1, %2, %3, %4};"
                 :: "l"(ptr), "f"(a), "f"(b), "f"(c), "f"(d) : "memory");
}

// 2 nodes x 32 outputs: one k-step. Wr warp-uniform -> true broadcast LDS.
static __device__ __forceinline__ void step2(ull* acc0, ull* acc1,
                                             const float* Wr, float a0, float a1) {
    const ulonglong2* w = (const ulonglong2*)Wr;
    ull A0 = pack2(a0, a0), A1 = pack2(a1, a1);
#pragma unroll
    for (int j = 0; j < 8; j++) {
        ulonglong2 wv = w[j];
        fma2(acc0[2 * j], A0, wv.x); fma2(acc0[2 * j + 1], A0, wv.y);
        fma2(acc1[2 * j], A1, wv.x); fma2(acc1[2 * j + 1], A1, wv.y);
    }
}

static __device__ __forceinline__ void init_acc(ull* acc0, ull* acc1,
                                                const float* bias32) {
    const ulonglong2* bb = (const ulonglong2*)bias32;
#pragma unroll
    for (int j = 0; j < 8; j++) {
        ulonglong2 b = bb[j];
        acc0[2 * j] = b.x; acc0[2 * j + 1] = b.y;
        acc1[2 * j] = b.x; acc1[2 * j + 1] = b.y;
    }
}

static __device__ __forceinline__ void store32(float* dst, const ull* acc) {
#pragma unroll
    for (int j = 0; j < 8; j++) {
        float l0, h0, l1, h1;
        unpack2(acc[2 * j], l0, h0);
        unpack2(acc[2 * j + 1], l1, h1);
        ((float4*)dst)[j] = make_float4(l0, h0, l1, h1);
    }
}

// ---------------- k0: zero degree arrays only -----------------------------------
__global__ void k_zero() {
    int i = blockIdx.x * blockDim.x + threadIdx.x;
    if (i < NN / 4) {
        float4 z = make_float4(0.f, 0.f, 0.f, 0.f);
        reinterpret_cast<float4*>(g_degf)[i] = z;
        reinterpret_cast<float4*>(g_degb)[i] = z;
    }
}

// ---------------- k1: weighted degrees -----------------------------------------
__global__ void k_deg(const int* __restrict__ ei, const float* __restrict__ ew) {
    int e = blockIdx.x * blockDim.x + threadIdx.x;
    if (e >= EE) return;
    int   s = ei[e];
    int   t = ei[EE + e];
    float w = ew[e];
    if (s == t || w == 0.f) return;
    atomicAdd(&g_degf[t], w);
    atomicAdd(&g_degb[s], w);
}

__global__ void k_rdeg() {
    int n = blockIdx.x * blockDim.x + threadIdx.x;
    if (n >= NN) return;
    float df = g_degf[n];
    float db = g_degb[n];
    g_degf[n] = (df > 0.f) ? (1.0f / df) : 1.0f;
    g_degb[n] = (db > 0.f) ? (1.0f / db) : 1.0f;
}

// ---------------- k2: input projection (2 nodes x 32 outs / thread) ------------
// Mapping: warp w, lane l; r = w&1 (WARP-UNIFORM output half), wp = w>>1.
// Nodes n0 = blk*256 + wp*64 + l, n1 = n0 + 32. Epilogue also zeroes outf/outb.
__global__ __launch_bounds__(256, 2) void k_proj2(const float* __restrict__ x,
                                                  const float* __restrict__ xh,
                                                  const float* __restrict__ h,
                                                  const float* __restrict__ Win,
                                                  const float* __restrict__ bin) {
    __shared__ __align__(16) float Ws[INCH * HH];   // 41216 B
    int tid = threadIdx.x;
    for (int i = tid; i < INCH * HH; i += 256) Ws[i] = Win[i];
    __syncthreads();

    int w = tid >> 5, l = tid & 31;
    int r  = w & 1;                  // warp-uniform
    int wp = w >> 1;
    int n0 = blockIdx.x * 256 + wp * 64 + l;
    int n1 = n0 + 32;
    int m0 = min(n0, NN - 1), m1 = min(n1, NN - 1);

    ull acc0[16], acc1[16];
    init_acc(acc0, acc1, bin + 32 * r);
    const float* W = Ws + 32 * r;

    // k = 0 : x
    step2(acc0, acc1, W, x[m0], x[m1]);

    // k = 1..96 : x_hat_1
    const float4* A0 = (const float4*)(xh + (size_t)m0 * 96);
    const float4* A1 = (const float4*)(xh + (size_t)m1 * 96);
#pragma unroll 2
    for (int kk = 0; kk < 24; kk++) {
        float4 a = A0[kk], b = A1[kk];
        const float* Wk = W + (1 + 4 * kk) * HH;
        step2(acc0, acc1, Wk,          a.x, b.x);
        step2(acc0, acc1, Wk + HH,     a.y, b.y);
        step2(acc0, acc1, Wk + 2 * HH, a.z, b.z);
        step2(acc0, acc1, Wk + 3 * HH, a.w, b.w);
    }
    // k = 97..160 : h
    const float4* H0 = (const float4*)(h + (size_t)m0 * 64);
    const float4* H1 = (const float4*)(h + (size_t)m1 * 64);
#pragma unroll 2
    for (int kk = 0; kk < 16; kk++) {
        float4 a = H0[kk], b = H1[kk];
        const float* Wk = W + (97 + 4 * kk) * HH;
        step2(acc0, acc1, Wk,          a.x, b.x);
        step2(acc0, acc1, Wk + HH,     a.y, b.y);
        step2(acc0, acc1, Wk + 2 * HH, a.z, b.z);
        step2(acc0, acc1, Wk + 3 * HH, a.w, b.w);
    }

    float4 z = make_float4(0.f, 0.f, 0.f, 0.f);
    if (n0 < NN) {
        store32(g_xin + (size_t)n0 * 64 + 32 * r, acc0);
        float4* zf = (float4*)(g_outf + (size_t)n0 * 64 + 32 * r);
        float4* zb = (float4*)(g_outb + (size_t)n0 * 64 + 32 * r);
#pragma unroll
        for (int j = 0; j < 8; j++) { zf[j] = z; zb[j] = z; }
    }
    if (n1 < NN) {
        store32(g_xin + (size_t)n1 * 64 + 32 * r, acc1);
        float4* zf = (float4*)(g_outf + (size_t)n1 * 64 + 32 * r);
        float4* zb = (float4*)(g_outb + (size_t)n1 * 64 + 32 * r);
#pragma unroll
        for (int j = 0; j < 8; j++) { zf[j] = z; zb[j] = z; }
    }
}

// ---------------- k3: edge diffusion scatter -----------------------------------
__global__ void k_diff(const int* __restrict__ ei, const float* __restrict__ ew) {
    int idx = blockIdx.x * blockDim.x + threadIdx.x;
    int e = idx >> 4;
    int c = idx & 15;
    if (e >= EE) return;
    int   s = ei[e];
    int   t = ei[EE + e];
    float w = ew[e];
    if (s == t || w == 0.f) return;
    float wf = w * g_degf[t];
    float wb = w * g_degb[s];

    const float4* xin4 = reinterpret_cast<const float4*>(g_xin);
    float4 a = xin4[(size_t)s * 16 + c];
    red_add_v4(g_outf + (size_t)t * 64 + c * 4,
               wf * a.x, wf * a.y, wf * a.z, wf * a.w);

    float4 b = xin4[(size_t)t * 16 + c];
    red_add_v4(g_outb + (size_t)s * 64 + c * 4,
               wb * b.x, wb * b.y, wb * b.z, wb * b.w);
}

// ---------------- k4: filter GEMM (2 nodes x 32 outs) + out1/h epilogue --------
__global__ __launch_bounds__(256, 2) void k_filt2(const float* __restrict__ h,
                                                  const float* __restrict__ Wf,
                                                  const float* __restrict__ bf,
                                                  float* __restrict__ out1,
                                                  float* __restrict__ hout) {
    __shared__ __align__(16) float Ws[128 * HH];    // 32 KB
    int tid = threadIdx.x;
    for (int i = tid; i < 128 * HH; i += 256) Ws[i] = Wf[i];
    __syncthreads();

    int w = tid >> 5, l = tid & 31;
    int r  = w & 1;                  // warp-uniform
    int wp = w >> 1;
    int n0 = blockIdx.x * 256 + wp * 64 + l;
    int n1 = n0 + 32;
    int m0 = min(n0, NN - 1), m1 = min(n1, NN - 1);

    ull acc0[16], acc1[16];
    init_acc(acc0, acc1, bf + 32 * r);
    const float* W = Ws + 32 * r;

    const float4* F0 = (const float4*)(g_outf + (size_t)m0 * 64);
    const float4* F1 = (const float4*)(g_outf + (size_t)m1 * 64);
#pragma unroll 2
    for (int kk = 0; kk < 16; kk++) {
        float4 a = F0[kk], b = F1[kk];
        const float* Wk = W + (4 * kk) * HH;
        step2(acc0, acc1, Wk,          a.x, b.x);
        step2(acc0, acc1, Wk + HH,     a.y, b.y);
        step2(acc0, acc1, Wk + 2 * HH, a.z, b.z);
        step2(acc0, acc1, Wk + 3 * HH, a.w, b.w);
    }
    const float4* B0 = (const float4*)(g_outb + (size_t)m0 * 64);
    const float4* B1 = (const float4*)(g_outb + (size_t)m1 * 64);
#pragma unroll 2
    for (int kk = 0; kk < 16; kk++) {
        float4 a = B0[kk], b = B1[kk];
        const float* Wk = W + (64 + 4 * kk) * HH;
        step2(acc0, acc1, Wk,          a.x, b.x);
        step2(acc0, acc1, Wk + HH,     a.y, b.y);
        step2(acc0, acc1, Wk + 2 * HH, a.z, b.z);
        step2(acc0, acc1, Wk + 3 * HH, a.w, b.w);
    }

#pragma unroll
    for (int i = 0; i < 2; i++) {
        int gn = (i == 0) ? n0 : n1;
        if (gn >= NN) continue;
        store32(out1 + (size_t)gn * 128 + 32 * r, (i == 0) ? acc0 : acc1);
        const float4* hp = (const float4*)(h + (size_t)gn * 64 + 32 * r);
        float4* o2 = (float4*)(out1 + (size_t)gn * 128 + 64 + 32 * r);
        float4* ho = (float4*)(hout + (size_t)gn * 64 + 32 * r);
#pragma unroll
        for (int j = 0; j < 8; j++) { float4 v = hp[j]; o2[j] = v; ho[j] = v; }
    }
}

// ---------------- k5: fused GMM heads (2 nodes x one 32-wide head / thread) ----
// 384 threads: r = tid>>7 (0=mu,1=sigma,2=pi; warp-uniform), p = tid&127.
__global__ __launch_bounds__(384, 1) void k_heads2(const float* __restrict__ out1,
                                                   const float* __restrict__ Wm,
                                                   const float* __restrict__ bm,
                                                   const float* __restrict__ Wsg,
                                                   const float* __restrict__ bsg,
                                                   const float* __restrict__ Wp,
                                                   const float* __restrict__ bp,
                                                   float* __restrict__ gmm) {
    extern __shared__ float Ws[];                   // [128][96] = [mu|sigma|pi]
    int tid = threadIdx.x;
    for (int i = tid; i < 128 * 96; i += 384) {
        int k = i / 96, c = i - k * 96;
        Ws[i] = (c < 32) ? Wm[k * 32 + c]
              : (c < 64) ? Wsg[k * 32 + (c - 32)]
                         : Wp[k * 32 + (c - 64)];
    }
    __syncthreads();

    int r = tid >> 7;                // head selector (warp-uniform)
    int p = tid & 127;
    int n0 = blockIdx.x * 256 + 2 * p;
    int n1 = n0 + 1;
    int m0 = min(n0, NN - 1), m1 = min(n1, NN - 1);

    const float* bias = (r == 0) ? bm : (r == 1) ? bsg : bp;
    ull acc0[16], acc1[16];
    init_acc(acc0, acc1, bias);
    const float* W = Ws + 32 * r;

    const float4* A0 = (const float4*)(out1 + (size_t)m0 * 128);
    const float4* A1 = (const float4*)(out1 + (size_t)m1 * 128);
#pragma unroll 2
    for (int kk = 0; kk < 32; kk++) {
        float4 a = A0[kk], b = A1[kk];
        const float* Wk = W + (4 * kk) * 96;
        step2(acc0, acc1, Wk,          a.x, b.x);
        step2(acc0, acc1, Wk + 96,     a.y, b.y);
        step2(acc0, acc1, Wk + 192,    a.z, b.z);
        step2(acc0, acc1, Wk + 288,    a.w, b.w);
    }

#pragma unroll
    for (int i = 0; i < 2; i++) {
        int gn = (i == 0) ? n0 : n1;
        if (gn >= NN) break;
        ull* acc = (i == 0) ? acc0 : acc1;
        float v[32];
#pragma unroll
        for (int j = 0; j < 16; j++) unpack2(acc[j], v[2 * j], v[2 * j + 1]);

        if (r == 1) {                  // sigma = softplus
#pragma unroll
            for (int j = 0; j < 32; j++)
                v[j] = (v[j] > 20.f) ? v[j] : log1pf(__expf(v[j]));
        } else if (r == 2) {           // pi = softmax over 32 (in-thread)
            float m = v[0];
#pragma unroll
            for (int j = 1; j < 32; j++) m = fmaxf(m, v[j]);
            float s = 0.f;
#pragma unroll
            for (int j = 0; j < 32; j++) { v[j] = __expf(v[j] - m); s += v[j]; }
            float inv = 1.f / s;
#pragma unroll
            for (int j = 0; j < 32; j++) v[j] *= inv;
        }
        float4* o = (float4*)(gmm + (size_t)gn * 96 + 32 * r);
#pragma unroll
        for (int j = 0; j < 8; j++)
            o[j] = make_float4(v[4 * j], v[4 * j + 1], v[4 * j + 2], v[4 * j + 3]);
    }
}

// ---------------- launch -------------------------------------------------------
extern "C" void kernel_launch(void* const* d_in, const int* in_sizes, int n_in,
                              void* d_out, int out_size) {
    const float* x   = (const float*)d_in[0];
    const float* xh  = (const float*)d_in[1];
    const float* h   = (const float*)d_in[2];
    const int*   ei  = (const int*)d_in[3];
    const float* ew  = (const float*)d_in[4];
    const float* Win = (const float*)d_in[5];
    const float* bin = (const float*)d_in[6];
    const float* Wf  = (const float*)d_in[7];
    const float* bf  = (const float*)d_in[8];
    const float* Wm  = (const float*)d_in[9];
    const float* bm  = (const float*)d_in[10];
    const float* Wsg = (const float*)d_in[11];
    const float* bsg = (const float*)d_in[12];
    const float* Wp  = (const float*)d_in[13];
    const float* bp  = (const float*)d_in[14];

    float* out  = (float*)d_out;
    float* gmm  = out;                          // [N, 96]
    float* out1 = out + (size_t)NN * 96;        // [N, 128]
    float* hout = out1 + (size_t)NN * 128;      // [N, 64]

    const int SMEM_HEADS = 128 * 96 * 4;        // 49152
    cudaFuncSetAttribute(k_heads2, cudaFuncAttributeMaxDynamicSharedMemorySize,
                         SMEM_HEADS);

    int nb2 = (NN + 255) / 256;   // 391 blocks, 256 nodes each

    k_zero<<<(NN / 4 + 255) / 256, 256>>>();
    k_deg<<<(EE + 255) / 256, 256>>>(ei, ew);
    k_rdeg<<<(NN + 255) / 256, 256>>>();
    k_proj2<<<nb2, 256>>>(x, xh, h, Win, bin);
    k_diff<<<(EE * 16) / 256, 256>>>(ei, ew);
    k_filt2<<<nb2, 256>>>(h, Wf, bf, out1, hout);
    k_heads2<<<nb2, 384, SMEM_HEADS>>>(out1, Wm, bm, Wsg, bsg, Wp, bp, gmm);
}